// round 8
// baseline (speedup 1.0000x reference)
#include <cuda_runtime.h>
#include <math.h>

#define HD   512
#define BB   64
#define TT   512
#define FUT  96
#define FF   64
#define NB   128
#define THR  1024
#define XS   132            // xs row stride (words): reads 1wf, stores balanced

typedef unsigned long long u64;

__device__ float g_h0[2][HD * BB];
__device__ float g_h1[2][HD * BB];
__device__ float g_c0[HD * BB];
__device__ float g_c1[HD * BB];
__device__ float g_decx[FF * BB];
__device__ unsigned g_bar_cnt;
__device__ unsigned g_bar_gen;

__device__ __forceinline__ void fma2(u64 &acc, u64 a, u64 b) {
    asm("fma.rn.f32x2 %0, %1, %2, %0;" : "+l"(acc) : "l"(a), "l"(b));
}
__device__ __forceinline__ float unpack_sum(u64 a) {
    float lo, hi;
    asm("mov.b64 {%0,%1}, %2;" : "=f"(lo), "=f"(hi) : "l"(a));
    return lo + hi;
}
__device__ __forceinline__ float sigm(float x) { return 1.0f / (1.0f + expf(-x)); }

__device__ __forceinline__ void gbar() {
    __syncthreads();
    if (threadIdx.x == 0) {
        unsigned gen = *(volatile unsigned*)&g_bar_gen;
        __threadfence();
        unsigned arrived = atomicAdd(&g_bar_cnt, 1u);
        if (arrived == NB - 1) {
            atomicExch(&g_bar_cnt, 0u);
            __threadfence();
            *(volatile unsigned*)&g_bar_gen = gen + 1u;
        } else {
            while (*(volatile unsigned*)&g_bar_gen == gen) { }
            __threadfence();
        }
    }
    __syncthreads();
}

// ---------------------------------------------------------------------------
// Staging (transposed src [k][64] -> xs[b][k], stride XS).
// 128-k chunk: warp w owns k-rows 4w..4w+3; lane l owns cols (l, l+32).
// Stores: banks 4l mod 32 -> perfectly balanced (4 wf per STS = optimal).
// ---------------------------------------------------------------------------
__device__ __forceinline__ void ld128T(float r0[4], float r1[4],
                                       const float* __restrict__ src, int k0) {
    int w = threadIdx.x >> 5, l = threadIdx.x & 31;
    const float* p = src + (size_t)(k0 + 4 * w) * 64 + l;
#pragma unroll
    for (int kk = 0; kk < 4; kk++) { r0[kk] = p[kk * 64]; r1[kk] = p[kk * 64 + 32]; }
}
__device__ __forceinline__ void st128T(const float r0[4], const float r1[4], float* xs) {
    int w = threadIdx.x >> 5, l = threadIdx.x & 31;
    *(float4*)(xs + (size_t)l * XS + 4 * w)        = make_float4(r0[0], r0[1], r0[2], r0[3]);
    *(float4*)(xs + (size_t)(l + 32) * XS + 4 * w) = make_float4(r1[0], r1[1], r1[2], r1[3]);
}
// 64-k transposed chunk (decx): warps 0..15 only.
__device__ __forceinline__ void stage64T(float* xs, const float* __restrict__ src) {
    int w = threadIdx.x >> 5, l = threadIdx.x & 31;
    if (w < 16) {
        const float* p = src + (size_t)(4 * w) * 64 + l;
        float a0[4], a1[4];
#pragma unroll
        for (int kk = 0; kk < 4; kk++) { a0[kk] = p[kk * 64]; a1[kk] = p[kk * 64 + 32]; }
        *(float4*)(xs + (size_t)l * XS + 4 * w)        = make_float4(a0[0], a0[1], a0[2], a0[3]);
        *(float4*)(xs + (size_t)(l + 32) * XS + 4 * w) = make_float4(a1[0], a1[1], a1[2], a1[3]);
    }
}
// 64-k row-major chunk (input_seq row t): one float4 per thread.
__device__ __forceinline__ void stage64R(float* xs, const float* __restrict__ src) {
    int i = threadIdx.x;
    int b = i >> 4, gq = i & 15;
    float4 v = *(const float4*)(src + (size_t)b * (TT * FF) + gq * 4);
    *(float4*)(xs + (size_t)b * XS + gq * 4) = v;
}

// ---------------------------------------------------------------------------
// Gate accumulation: NG granules (4k each). x: 8 distinct b per warp -> 1 wf.
// w: 4 jj, stride GS per gate -> 1 wf each.
// ---------------------------------------------------------------------------
template<int NG, int GS>
__device__ __forceinline__ void accG(u64 acc[4], const float* x, const float* w) {
#pragma unroll
    for (int s = 0; s < NG; s++) {
        ulonglong2 xv = *(const ulonglong2*)(x + 4 * s);
        ulonglong2 wv;
        wv = *(const ulonglong2*)(w + 4 * s);          fma2(acc[0], xv.x, wv.x); fma2(acc[0], xv.y, wv.y);
        wv = *(const ulonglong2*)(w + GS + 4 * s);     fma2(acc[1], xv.x, wv.x); fma2(acc[1], xv.y, wv.y);
        wv = *(const ulonglong2*)(w + 2 * GS + 4 * s); fma2(acc[2], xv.x, wv.x); fma2(acc[2], xv.y, wv.y);
        wv = *(const ulonglong2*)(w + 3 * GS + 4 * s); fma2(acc[3], xv.x, wv.x); fma2(acc[3], xv.y, wv.y);
    }
}

// Combine 4 split-K partials via cm, then gate math + c/h update (q==0 only).
__device__ __forceinline__ void combine_epi(u64 acc[4], float* cm, float4 bias,
                                            float* __restrict__ hnext,
                                            float* __restrict__ cbuf,
                                            int b, int q, int j, int t8) {
    ((float4*)cm)[threadIdx.x] = make_float4(unpack_sum(acc[0]), unpack_sum(acc[1]),
                                             unpack_sum(acc[2]), unpack_sum(acc[3]));
    __syncthreads();
    if (q == 0) {
        float4 a0 = ((float4*)cm)[t8];
        float4 a1 = ((float4*)cm)[t8 + 256];
        float4 a2 = ((float4*)cm)[t8 + 512];
        float4 a3 = ((float4*)cm)[t8 + 768];
        float gi = a0.x + a1.x + a2.x + a3.x + bias.x;
        float gf = a0.y + a1.y + a2.y + a3.y + bias.y;
        float gg = a0.z + a1.z + a2.z + a3.z + bias.z;
        float go = a0.w + a1.w + a2.w + a3.w + bias.w;
        int idx = j * 64 + b;
        float c = sigm(gf) * cbuf[idx] + sigm(gi) * tanhf(gg);
        cbuf[idx]  = c;
        hnext[idx] = sigm(go) * tanhf(c);
    }
}

// ---------------------------------------------------------------------------
// L1-style cell: K = 512 (x) + 512 (h), 8 pipelined chunks, 1 sync each.
// ---------------------------------------------------------------------------
__device__ __noinline__ void cell512(const float* Wi, const float* Wh,
                                     const float* __restrict__ srcx,
                                     const float* __restrict__ srch,
                                     float* __restrict__ hnext,
                                     float* __restrict__ cbuf,
                                     float* xs0, float* xs1, float* cm,
                                     float4 bias, int b, int jj, int q, int j, int t8) {
    u64 acc[4] = {0ull, 0ull, 0ull, 0ull};
    float r0[4], r1[4];
    float* bufs[2] = {xs0, xs1};
    const size_t xoff = (size_t)b * XS + q * 32;

    ld128T(r0, r1, srcx, 0);
    st128T(r0, r1, xs0);
#pragma unroll 1
    for (int c = 0; c < 8; c++) {
        if (c < 7) ld128T(r0, r1, (c + 1 < 4) ? srcx : srch, ((c + 1) & 3) * 128);
        __syncthreads();
        if (c < 7) st128T(r0, r1, bufs[(c + 1) & 1]);
        const float* W = (c < 4 ? Wi : Wh) + (size_t)jj * 516 + (c & 3) * 128 + q * 32;
        accG<8, 2064>(acc, bufs[c & 1] + xoff, W);
    }
    combine_epi(acc, cm, bias, hnext, cbuf, b, q, j, t8);
}

// ---------------------------------------------------------------------------
// L0-style cell: K = 64 (x) + 512 (h). Input 64k chunk + 4 pipelined chunks.
// ---------------------------------------------------------------------------
__device__ __noinline__ void cell64(const float* Wi, const float* Wh,
                                    const float* __restrict__ x64T,
                                    const float* __restrict__ x64R,
                                    const float* __restrict__ srch,
                                    float* __restrict__ hnext,
                                    float* __restrict__ cbuf,
                                    float* xs0, float* xs1, float* cm,
                                    float4 bias, int b, int jj, int q, int j, int t8) {
    u64 acc[4] = {0ull, 0ull, 0ull, 0ull};
    float r0[4], r1[4];
    float* bufs[2] = {xs1, xs0};

    if (x64R) stage64R(xs0, x64R);
    else      stage64T(xs0, x64T);
    ld128T(r0, r1, srch, 0);
    __syncthreads();
    st128T(r0, r1, xs1);
    accG<4, 288>(acc, xs0 + (size_t)b * XS + q * 16, Wi + (size_t)jj * 72 + q * 16);

    const size_t xoff = (size_t)b * XS + q * 32;
#pragma unroll 1
    for (int c = 0; c < 4; c++) {
        if (c < 3) ld128T(r0, r1, srch, (c + 1) * 128);
        __syncthreads();
        if (c < 3) st128T(r0, r1, bufs[(c + 1) & 1]);
        accG<8, 2064>(acc, bufs[c & 1] + xoff, Wh + (size_t)jj * 516 + c * 128 + q * 32);
    }
    combine_epi(acc, cm, bias, hnext, cbuf, b, q, j, t8);
}

// ---------------------------------------------------------------------------
// Decoder FC (CTAs < 64; f = blockIdx.x): out = h1 . fcrow + fcb
// ---------------------------------------------------------------------------
__device__ __noinline__ void fc_step(const float* fcrow, float fcbias,
                                     const float* __restrict__ h1,
                                     float* __restrict__ out, int d,
                                     float* xs0, float* xs1, float* cm, int f) {
    int tid = threadIdx.x, b = tid & 63, qq = tid >> 6;  // 16-way K split
    u64 acc = 0ull;
    float r0[4], r1[4];
    float* bufs[2] = {xs0, xs1};
    ld128T(r0, r1, h1, 0);
    st128T(r0, r1, xs0);
#pragma unroll 1
    for (int c = 0; c < 4; c++) {
        if (c < 3) ld128T(r0, r1, h1, (c + 1) * 128);
        __syncthreads();
        if (c < 3) st128T(r0, r1, bufs[(c + 1) & 1]);
        if ((qq >> 2) == c) {
            const float* x = bufs[c & 1] + (size_t)b * XS + (qq & 3) * 32;
            const float* w = fcrow + qq * 32;
#pragma unroll
            for (int s = 0; s < 8; s++) {
                ulonglong2 xv = *(const ulonglong2*)(x + 4 * s);
                ulonglong2 wv = *(const ulonglong2*)(w + 4 * s);
                fma2(acc, xv.x, wv.x); fma2(acc, xv.y, wv.y);
            }
        }
    }
    __syncthreads();
    cm[qq * 64 + b] = unpack_sum(acc);
    __syncthreads();
    if (qq == 0) {
        float v = fcbias;
#pragma unroll
        for (int m = 0; m < 16; m++) v += cm[m * 64 + b];
        out[(size_t)b * (FUT * FF) + (size_t)d * FF + f] = v;
        g_decx[f * 64 + b] = v;
    }
}

// Copy 16 weight rows (4 gates x 4 j), padded row stride RS.
__device__ __forceinline__ void loadW(float* dst, const float* __restrict__ src,
                                      int K, int RS, int j0) {
    int Kq = K >> 2, n = 16 * Kq;
    for (int i = threadIdx.x; i < n; i += THR) {
        int rr = i / Kq, kq = i - rr * Kq;
        int g = rr >> 2, j2 = rr & 3;
        float4 v = *(const float4*)(src + (size_t)(g * HD + j0 + j2) * K + kq * 4);
        *(float4*)(dst + (size_t)rr * RS + kq * 4) = v;
    }
}

// ---------------------------------------------------------------------------
// SMEM (floats): W0i@0(1152) W0h@1152(8256) W1i@9408(8256) W1h@17664(8256)
//   fcrow@25920(512) cm@26432(4096) xs0@30528(8448) xs1@38976(8448) = 47424 fl
// ---------------------------------------------------------------------------
__global__ void __launch_bounds__(THR, 1)
lstm_persist(const float* __restrict__ in,
             const float* __restrict__ eWih0, const float* __restrict__ eWhh0,
             const float* __restrict__ ebih0, const float* __restrict__ ebhh0,
             const float* __restrict__ eWih1, const float* __restrict__ eWhh1,
             const float* __restrict__ ebih1, const float* __restrict__ ebhh1,
             const float* __restrict__ dWih0, const float* __restrict__ dWhh0,
             const float* __restrict__ dbih0, const float* __restrict__ dbhh0,
             const float* __restrict__ dWih1, const float* __restrict__ dWhh1,
             const float* __restrict__ dbih1, const float* __restrict__ dbhh1,
             const float* __restrict__ fcW,   const float* __restrict__ fcb,
             float* __restrict__ out) {
    extern __shared__ float sm[];
    float* W0i   = sm;
    float* W0h   = sm + 1152;
    float* W1i   = sm + 9408;
    float* W1h   = sm + 17664;
    float* fcrow = sm + 25920;
    float* cm    = sm + 26432;
    float* xs0   = sm + 30528;
    float* xs1   = sm + 38976;

    const int tid  = threadIdx.x;
    const int q    = tid >> 8;           // split-K quarter
    const int t8   = tid & 255;
    const int b_hi = t8 >> 5;
    const int jj   = (t8 >> 3) & 3;
    const int b_lo = t8 & 7;
    const int b    = b_hi * 8 + b_lo;
    const int j0   = blockIdx.x * 4, j = j0 + jj;

    loadW(W0i, eWih0, 64, 72,  j0);
    loadW(W0h, eWhh0, HD, 516, j0);
    loadW(W1i, eWih1, HD, 516, j0);
    loadW(W1h, eWhh1, HD, 516, j0);
    float fcbias = 0.f;
    if (blockIdx.x < 64) {
        for (int i = tid; i < HD; i += THR) fcrow[i] = fcW[(size_t)blockIdx.x * HD + i];
        fcbias = fcb[blockIdx.x];
    }

    {   // zero persistent state
        int i = blockIdx.x * THR + tid;
        if (i < HD * BB) { g_h0[0][i] = 0.f; g_h1[0][i] = 0.f; g_c0[i] = 0.f; g_c1[i] = 0.f; }
        if (i < FF * BB) g_decx[i] = 0.f;
    }

    float4 b_e0 = make_float4(ebih0[j] + ebhh0[j],
                              ebih0[HD + j] + ebhh0[HD + j],
                              ebih0[2 * HD + j] + ebhh0[2 * HD + j],
                              ebih0[3 * HD + j] + ebhh0[3 * HD + j]);
    float4 b_e1 = make_float4(ebih1[j] + ebhh1[j],
                              ebih1[HD + j] + ebhh1[HD + j],
                              ebih1[2 * HD + j] + ebhh1[2 * HD + j],
                              ebih1[3 * HD + j] + ebhh1[3 * HD + j]);
    float4 b_d0 = make_float4(dbih0[j] + dbhh0[j],
                              dbih0[HD + j] + dbhh0[HD + j],
                              dbih0[2 * HD + j] + dbhh0[2 * HD + j],
                              dbih0[3 * HD + j] + dbhh0[3 * HD + j]);
    float4 b_d1 = make_float4(dbih1[j] + dbhh1[j],
                              dbih1[HD + j] + dbhh1[HD + j],
                              dbih1[2 * HD + j] + dbhh1[2 * HD + j],
                              dbih1[3 * HD + j] + dbhh1[3 * HD + j]);

    gbar();

    // ===================== encoder =====================
    cell64(W0i, W0h, nullptr, in, g_h0[0], g_h0[1], g_c0,
           xs0, xs1, cm, b_e0, b, jj, q, j, t8);
    gbar();
#pragma unroll 1
    for (int t = 0; t < TT - 1; t++) {
        int s = t & 1;
        cell512(W1i, W1h, g_h0[s ^ 1], g_h1[s], g_h1[s ^ 1], g_c1,
                xs0, xs1, cm, b_e1, b, jj, q, j, t8);
        cell64(W0i, W0h, nullptr, in + (size_t)(t + 1) * FF,
               g_h0[s ^ 1], g_h0[s], g_c0,
               xs0, xs1, cm, b_e0, b, jj, q, j, t8);
        gbar();
    }
    cell512(W1i, W1h, g_h0[0], g_h1[1], g_h1[0], g_c1,
            xs0, xs1, cm, b_e1, b, jj, q, j, t8);
    gbar();
    // h0 current = slot 0, h1 current = slot 0

    // swap to decoder weights
    loadW(W0i, dWih0, 64, 72,  j0);
    loadW(W0h, dWhh0, HD, 516, j0);
    loadW(W1i, dWih1, HD, 516, j0);
    loadW(W1h, dWhh1, HD, 516, j0);
    __syncthreads();

    // ===================== decoder =====================
#pragma unroll 1
    for (int d = 0; d < FUT; d++) {
        int p = d & 1;
        if (d == 0)
            cell64(W0i, W0h, nullptr, in + (size_t)(TT - 1) * FF,
                   g_h0[p], g_h0[p ^ 1], g_c0, xs0, xs1, cm, b_d0, b, jj, q, j, t8);
        else
            cell64(W0i, W0h, g_decx, nullptr,
                   g_h0[p], g_h0[p ^ 1], g_c0, xs0, xs1, cm, b_d0, b, jj, q, j, t8);
        gbar();
        cell512(W1i, W1h, g_h0[p ^ 1], g_h1[p], g_h1[p ^ 1], g_c1,
                xs0, xs1, cm, b_d1, b, jj, q, j, t8);
        gbar();
        if (blockIdx.x < 64)
            fc_step(fcrow, fcbias, g_h1[p ^ 1], out, d, xs0, xs1, cm, blockIdx.x);
        gbar();
    }
}

extern "C" void kernel_launch(void* const* d_in, const int* in_sizes, int n_in,
                              void* d_out, int out_size) {
    const size_t SMEM = 47424 * sizeof(float);   // 189,696 B
    cudaFuncSetAttribute(lstm_persist, cudaFuncAttributeMaxDynamicSharedMemorySize,
                         (int)SMEM);
    lstm_persist<<<NB, THR, SMEM>>>(
        (const float*)d_in[0],
        (const float*)d_in[1],  (const float*)d_in[2],
        (const float*)d_in[3],  (const float*)d_in[4],
        (const float*)d_in[5],  (const float*)d_in[6],
        (const float*)d_in[7],  (const float*)d_in[8],
        (const float*)d_in[9],  (const float*)d_in[10],
        (const float*)d_in[11], (const float*)d_in[12],
        (const float*)d_in[13], (const float*)d_in[14],
        (const float*)d_in[15], (const float*)d_in[16],
        (const float*)d_in[17], (const float*)d_in[18],
        (float*)d_out);
}

// round 9
// speedup vs baseline: 1.2956x; 1.2956x over previous
#include <cuda_runtime.h>
#include <math.h>

#define HD   512
#define BB   64
#define TT   512
#define FUT  96
#define FF   64
#define NB   128
#define THR  512
#define XS   132            // xs row stride (words)

typedef unsigned long long u64;

__device__ float g_h0[2][HD * BB];
__device__ float g_h1[2][HD * BB];
__device__ float g_c0[HD * BB];
__device__ float g_c1[HD * BB];
__device__ float g_decx[FF * BB];
__device__ unsigned g_bar_cnt;
__device__ unsigned g_bar_gen;

__device__ __forceinline__ void fma2(u64 &acc, u64 a, u64 b) {
    asm("fma.rn.f32x2 %0, %1, %2, %0;" : "+l"(acc) : "l"(a), "l"(b));
}
__device__ __forceinline__ float unpack_sum(u64 a) {
    float lo, hi;
    asm("mov.b64 {%0,%1}, %2;" : "=f"(lo), "=f"(hi) : "l"(a));
    return lo + hi;
}
// fast activations (__expf err ~1e-6; safe at all magnitudes)
__device__ __forceinline__ float sigm(float x)  { return __fdividef(1.f, 1.f + __expf(-x)); }
__device__ __forceinline__ float tanh_(float x) { return __fdividef(2.f, 1.f + __expf(-2.f * x)) - 1.f; }

__device__ __forceinline__ void gbar() {
    __syncthreads();
    if (threadIdx.x == 0) {
        unsigned gen = *(volatile unsigned*)&g_bar_gen;
        __threadfence();
        unsigned arrived = atomicAdd(&g_bar_cnt, 1u);
        if (arrived == NB - 1) {
            atomicExch(&g_bar_cnt, 0u);
            __threadfence();
            *(volatile unsigned*)&g_bar_gen = gen + 1u;
        } else {
            while (*(volatile unsigned*)&g_bar_gen == gen) { }
            __threadfence();
        }
    }
    __syncthreads();
}

// ---------------------------------------------------------------------------
// Staging: transposed src [k][64] -> xs[b][k] (stride XS).
// 128-k chunk, 16 warps: warp w owns k-rows 8w..8w+7; lane l owns cols l, l+32.
// ---------------------------------------------------------------------------
__device__ __forceinline__ void ldT(float r0[8], float r1[8],
                                    const float* __restrict__ src, int k0) {
    int w = threadIdx.x >> 5, l = threadIdx.x & 31;
    const float* p = src + (size_t)(k0 + 8 * w) * 64 + l;
#pragma unroll
    for (int kk = 0; kk < 8; kk++) { r0[kk] = p[kk * 64]; r1[kk] = p[kk * 64 + 32]; }
}
__device__ __forceinline__ void stT(const float r0[8], const float r1[8], float* xs) {
    int w = threadIdx.x >> 5, l = threadIdx.x & 31;
    float* p0 = xs + (size_t)l * XS + 8 * w;
    float* p1 = xs + (size_t)(l + 32) * XS + 8 * w;
    *(float4*)p0       = make_float4(r0[0], r0[1], r0[2], r0[3]);
    *(float4*)(p0 + 4) = make_float4(r0[4], r0[5], r0[6], r0[7]);
    *(float4*)p1       = make_float4(r1[0], r1[1], r1[2], r1[3]);
    *(float4*)(p1 + 4) = make_float4(r1[4], r1[5], r1[6], r1[7]);
}
// 64-k transposed chunk (decx): 16 warps x 4 k-rows.
__device__ __forceinline__ void stage64T(float* xs, const float* __restrict__ src) {
    int w = threadIdx.x >> 5, l = threadIdx.x & 31;
    const float* p = src + (size_t)(4 * w) * 64 + l;
    float a0[4], a1[4];
#pragma unroll
    for (int kk = 0; kk < 4; kk++) { a0[kk] = p[kk * 64]; a1[kk] = p[kk * 64 + 32]; }
    *(float4*)(xs + (size_t)l * XS + 4 * w)        = make_float4(a0[0], a0[1], a0[2], a0[3]);
    *(float4*)(xs + (size_t)(l + 32) * XS + 4 * w) = make_float4(a1[0], a1[1], a1[2], a1[3]);
}
// 64-k row-major chunk (input_seq row t)
__device__ __forceinline__ void stage64R(float* xs, const float* __restrict__ src) {
    for (int i = threadIdx.x; i < 1024; i += THR) {
        int bb = i >> 4, gq = i & 15;
        float4 v = *(const float4*)(src + (size_t)bb * (TT * FF) + gq * 4);
        *(float4*)(xs + (size_t)bb * XS + gq * 4) = v;
    }
}

// ---------------------------------------------------------------------------
// Gate accumulation, 2 batch elements per thread: each w LDS.128 feeds 4 fma2.
// acc[2g] = gate g for b, acc[2g+1] = gate g for b+32.
// ---------------------------------------------------------------------------
template<int NG, int GS>
__device__ __forceinline__ void accG2(u64 acc[8], const float* xa, const float* xb,
                                      const float* w) {
#pragma unroll
    for (int s = 0; s < NG; s++) {
        ulonglong2 xv = *(const ulonglong2*)(xa + 4 * s);
        ulonglong2 yv = *(const ulonglong2*)(xb + 4 * s);
        ulonglong2 wv;
        wv = *(const ulonglong2*)(w + 4 * s);
        fma2(acc[0], xv.x, wv.x); fma2(acc[0], xv.y, wv.y);
        fma2(acc[1], yv.x, wv.x); fma2(acc[1], yv.y, wv.y);
        wv = *(const ulonglong2*)(w + GS + 4 * s);
        fma2(acc[2], xv.x, wv.x); fma2(acc[2], xv.y, wv.y);
        fma2(acc[3], yv.x, wv.x); fma2(acc[3], yv.y, wv.y);
        wv = *(const ulonglong2*)(w + 2 * GS + 4 * s);
        fma2(acc[4], xv.x, wv.x); fma2(acc[4], xv.y, wv.y);
        fma2(acc[5], yv.x, wv.x); fma2(acc[5], yv.y, wv.y);
        wv = *(const ulonglong2*)(w + 3 * GS + 4 * s);
        fma2(acc[6], xv.x, wv.x); fma2(acc[6], xv.y, wv.y);
        fma2(acc[7], yv.x, wv.x); fma2(acc[7], yv.y, wv.y);
    }
}

// Combine 4 q-partials, gate math, c/h update (256 reducer threads).
__device__ __forceinline__ void combine2(u64 acc[8], float* cm, const float4* biasS,
                                         float* __restrict__ hnext,
                                         float* __restrict__ cbuf,
                                         int b, int jj, int q, int j0) {
    float4* cm4 = (float4*)cm;
    cm4[q * 256 + jj * 64 + b]      = make_float4(unpack_sum(acc[0]), unpack_sum(acc[2]),
                                                  unpack_sum(acc[4]), unpack_sum(acc[6]));
    cm4[q * 256 + jj * 64 + b + 32] = make_float4(unpack_sum(acc[1]), unpack_sum(acc[3]),
                                                  unpack_sum(acc[5]), unpack_sum(acc[7]));
    __syncthreads();
    int tid = threadIdx.x;
    if (tid < 256) {
        int bb = tid & 63, j2 = tid >> 6;
        int s = j2 * 64 + bb;
        float4 a0 = cm4[s], a1 = cm4[s + 256], a2 = cm4[s + 512], a3 = cm4[s + 768];
        float4 bias = biasS[j2];
        float gi = a0.x + a1.x + a2.x + a3.x + bias.x;
        float gf = a0.y + a1.y + a2.y + a3.y + bias.y;
        float gg = a0.z + a1.z + a2.z + a3.z + bias.z;
        float go = a0.w + a1.w + a2.w + a3.w + bias.w;
        int idx = (j0 + j2) * 64 + bb;
        float c = sigm(gf) * cbuf[idx] + sigm(gi) * tanh_(gg);
        cbuf[idx]  = c;
        hnext[idx] = sigm(go) * tanh_(c);
    }
}

// ---------------------------------------------------------------------------
// K = 512 + 512 cell: 8 pipelined chunks; acc BEFORE store (hides LDG latency).
// ---------------------------------------------------------------------------
__device__ __noinline__ void cell512(const float* Wi, const float* Wh,
                                     const float* __restrict__ srcx,
                                     const float* __restrict__ srch,
                                     float* __restrict__ hnext,
                                     float* __restrict__ cbuf,
                                     float* xs0, float* xs1, float* cm,
                                     const float4* biasS, int b, int jj, int q, int j0) {
    u64 acc[8] = {0ull,0ull,0ull,0ull,0ull,0ull,0ull,0ull};
    float r0[8], r1[8];
    float* bufs[2] = {xs0, xs1};
    ldT(r0, r1, srcx, 0);
    stT(r0, r1, xs0);
#pragma unroll 1
    for (int c = 0; c < 8; c++) {
        if (c < 7) ldT(r0, r1, (c + 1 < 4) ? srcx : srch, ((c + 1) & 3) * 128);
        __syncthreads();
        const float* xp = bufs[c & 1] + q * 32;
        const float* W  = (c < 4 ? Wi : Wh) + (size_t)jj * 516 + (c & 3) * 128 + q * 32;
        accG2<8, 2064>(acc, xp + (size_t)b * XS, xp + (size_t)(b + 32) * XS, W);
        if (c < 7) stT(r0, r1, bufs[(c + 1) & 1]);
    }
    combine2(acc, cm, biasS, hnext, cbuf, b, jj, q, j0);
}

// ---------------------------------------------------------------------------
// K = 64 + 512 cell.
// ---------------------------------------------------------------------------
__device__ __noinline__ void cell64(const float* Wi, const float* Wh,
                                    const float* __restrict__ x64T,
                                    const float* __restrict__ x64R,
                                    const float* __restrict__ srch,
                                    float* __restrict__ hnext,
                                    float* __restrict__ cbuf,
                                    float* xs0, float* xs1, float* cm,
                                    const float4* biasS, int b, int jj, int q, int j0) {
    u64 acc[8] = {0ull,0ull,0ull,0ull,0ull,0ull,0ull,0ull};
    float r0[8], r1[8];
    float* bufs[2] = {xs1, xs0};
    if (x64R) stage64R(xs0, x64R);
    else      stage64T(xs0, x64T);
    ldT(r0, r1, srch, 0);
    __syncthreads();
    accG2<4, 288>(acc, xs0 + (size_t)b * XS + q * 16,
                  xs0 + (size_t)(b + 32) * XS + q * 16,
                  Wi + (size_t)jj * 72 + q * 16);
    stT(r0, r1, xs1);
#pragma unroll 1
    for (int c = 0; c < 4; c++) {
        if (c < 3) ldT(r0, r1, srch, (c + 1) * 128);
        __syncthreads();
        const float* xp = bufs[c & 1] + q * 32;
        accG2<8, 2064>(acc, xp + (size_t)b * XS, xp + (size_t)(b + 32) * XS,
                       Wh + (size_t)jj * 516 + c * 128 + q * 32);
        if (c < 3) stT(r0, r1, bufs[(c + 1) & 1]);
    }
    combine2(acc, cm, biasS, hnext, cbuf, b, jj, q, j0);
}

// ---------------------------------------------------------------------------
// Decoder FC (CTAs < 64; f = blockIdx.x)
// ---------------------------------------------------------------------------
__device__ __noinline__ void fc_step(const float* fcrow, float fcbias,
                                     const float* __restrict__ h1,
                                     float* __restrict__ out, int d,
                                     float* xs0, float* xs1, float* cm, int f) {
    int tid = threadIdx.x, bq = tid & 63, qq = tid >> 6;  // 8-way K split
    u64 acc = 0ull;
    float r0[8], r1[8];
    float* bufs[2] = {xs0, xs1};
    ldT(r0, r1, h1, 0);
    stT(r0, r1, xs0);
#pragma unroll 1
    for (int c = 0; c < 4; c++) {
        if (c < 3) ldT(r0, r1, h1, (c + 1) * 128);
        __syncthreads();
        if ((qq >> 1) == c) {
            const float* x = bufs[c & 1] + (size_t)bq * XS + (qq & 1) * 64;
            const float* w = fcrow + qq * 64;
#pragma unroll
            for (int s2 = 0; s2 < 16; s2++) {
                ulonglong2 xv = *(const ulonglong2*)(x + 4 * s2);
                ulonglong2 wv = *(const ulonglong2*)(w + 4 * s2);
                fma2(acc, xv.x, wv.x); fma2(acc, xv.y, wv.y);
            }
        }
        if (c < 3) stT(r0, r1, bufs[(c + 1) & 1]);
    }
    __syncthreads();
    cm[qq * 64 + bq] = unpack_sum(acc);
    __syncthreads();
    if (qq == 0) {
        float v = fcbias;
#pragma unroll
        for (int m = 0; m < 8; m++) v += cm[m * 64 + bq];
        out[(size_t)bq * (FUT * FF) + (size_t)d * FF + f] = v;
        g_decx[f * 64 + bq] = v;
    }
}

// Copy 16 weight rows (4 gates x 4 j), padded row stride RS.
__device__ __forceinline__ void loadW(float* dst, const float* __restrict__ src,
                                      int K, int RS, int j0) {
    int Kq = K >> 2, n = 16 * Kq;
    for (int i = threadIdx.x; i < n; i += THR) {
        int rr = i / Kq, kq = i - rr * Kq;
        int g = rr >> 2, j2 = rr & 3;
        float4 v = *(const float4*)(src + (size_t)(g * HD + j0 + j2) * K + kq * 4);
        *(float4*)(dst + (size_t)rr * RS + kq * 4) = v;
    }
}

// ---------------------------------------------------------------------------
// SMEM (floats): W0i@0(1152) W0h@1152(8256) W1i@9408(8256) W1h@17664(8256)
//  fcrow@25920(512) biasS@26432(64) cm@26496(4096) xs0@30592(8448)
//  xs1@39040(8448)  total 47488 fl = 189,952 B
// ---------------------------------------------------------------------------
__global__ void __launch_bounds__(THR, 1)
lstm_persist(const float* __restrict__ in,
             const float* __restrict__ eWih0, const float* __restrict__ eWhh0,
             const float* __restrict__ ebih0, const float* __restrict__ ebhh0,
             const float* __restrict__ eWih1, const float* __restrict__ eWhh1,
             const float* __restrict__ ebih1, const float* __restrict__ ebhh1,
             const float* __restrict__ dWih0, const float* __restrict__ dWhh0,
             const float* __restrict__ dbih0, const float* __restrict__ dbhh0,
             const float* __restrict__ dWih1, const float* __restrict__ dWhh1,
             const float* __restrict__ dbih1, const float* __restrict__ dbhh1,
             const float* __restrict__ fcW,   const float* __restrict__ fcb,
             float* __restrict__ out) {
    extern __shared__ float sm[];
    float*  W0i    = sm;
    float*  W0h    = sm + 1152;
    float*  W1i    = sm + 9408;
    float*  W1h    = sm + 17664;
    float*  fcrow  = sm + 25920;
    float4* biasS4 = (float4*)(sm + 26432);
    float*  cm     = sm + 26496;
    float*  xs0    = sm + 30592;
    float*  xs1    = sm + 39040;

    const int tid   = threadIdx.x;
    const int q     = tid >> 7;          // 0..3 split-K quarter
    const int t7    = tid & 127;
    const int b_mid = t7 >> 5;
    const int jj    = (t7 >> 3) & 3;
    const int b_lo  = t7 & 7;
    const int b     = b_mid * 8 + b_lo;  // 0..31 (thread also handles b+32)
    const int j0    = blockIdx.x * 4;
    const int j     = j0 + jj;

    loadW(W0i, eWih0, 64, 72,  j0);
    loadW(W0h, eWhh0, HD, 516, j0);
    loadW(W1i, eWih1, HD, 516, j0);
    loadW(W1h, eWhh1, HD, 516, j0);
    float fcbias = 0.f;
    if (blockIdx.x < 64) {
        for (int i = tid; i < HD; i += THR) fcrow[i] = fcW[(size_t)blockIdx.x * HD + i];
        fcbias = fcb[blockIdx.x];
    }

    {   // zero persistent state
        for (int i = blockIdx.x * THR + tid; i < HD * BB; i += NB * THR) {
            g_h0[0][i] = 0.f; g_h1[0][i] = 0.f; g_c0[i] = 0.f; g_c1[i] = 0.f;
            if (i < FF * BB) g_decx[i] = 0.f;
        }
    }

    // combined biases -> smem (indexed by j2 in the reducer)
    if (q == 0 && b == 0) {
        biasS4[jj] = make_float4(ebih0[j] + ebhh0[j],
                                 ebih0[HD + j] + ebhh0[HD + j],
                                 ebih0[2 * HD + j] + ebhh0[2 * HD + j],
                                 ebih0[3 * HD + j] + ebhh0[3 * HD + j]);
        biasS4[4 + jj] = make_float4(ebih1[j] + ebhh1[j],
                                     ebih1[HD + j] + ebhh1[HD + j],
                                     ebih1[2 * HD + j] + ebhh1[2 * HD + j],
                                     ebih1[3 * HD + j] + ebhh1[3 * HD + j]);
        biasS4[8 + jj] = make_float4(dbih0[j] + dbhh0[j],
                                     dbih0[HD + j] + dbhh0[HD + j],
                                     dbih0[2 * HD + j] + dbhh0[2 * HD + j],
                                     dbih0[3 * HD + j] + dbhh0[3 * HD + j]);
        biasS4[12 + jj] = make_float4(dbih1[j] + dbhh1[j],
                                      dbih1[HD + j] + dbhh1[HD + j],
                                      dbih1[2 * HD + j] + dbhh1[2 * HD + j],
                                      dbih1[3 * HD + j] + dbhh1[3 * HD + j]);
    }

    gbar();

    // ===================== encoder =====================
    cell64(W0i, W0h, nullptr, in, g_h0[0], g_h0[1], g_c0,
           xs0, xs1, cm, biasS4, b, jj, q, j0);
    gbar();
#pragma unroll 1
    for (int t = 0; t < TT - 1; t++) {
        int s = t & 1;
        cell512(W1i, W1h, g_h0[s ^ 1], g_h1[s], g_h1[s ^ 1], g_c1,
                xs0, xs1, cm, biasS4 + 4, b, jj, q, j0);
        cell64(W0i, W0h, nullptr, in + (size_t)(t + 1) * FF,
               g_h0[s ^ 1], g_h0[s], g_c0,
               xs0, xs1, cm, biasS4, b, jj, q, j0);
        gbar();
    }
    cell512(W1i, W1h, g_h0[0], g_h1[1], g_h1[0], g_c1,
            xs0, xs1, cm, biasS4 + 4, b, jj, q, j0);
    gbar();
    // h0 current = slot 0, h1 current = slot 0

    // swap to decoder weights
    loadW(W0i, dWih0, 64, 72,  j0);
    loadW(W0h, dWhh0, HD, 516, j0);
    loadW(W1i, dWih1, HD, 516, j0);
    loadW(W1h, dWhh1, HD, 516, j0);
    __syncthreads();

    // ===================== decoder =====================
#pragma unroll 1
    for (int d = 0; d < FUT; d++) {
        int p = d & 1;
        if (d == 0)
            cell64(W0i, W0h, nullptr, in + (size_t)(TT - 1) * FF,
                   g_h0[p], g_h0[p ^ 1], g_c0, xs0, xs1, cm, biasS4 + 8, b, jj, q, j0);
        else
            cell64(W0i, W0h, g_decx, nullptr,
                   g_h0[p], g_h0[p ^ 1], g_c0, xs0, xs1, cm, biasS4 + 8, b, jj, q, j0);
        gbar();
        cell512(W1i, W1h, g_h0[p ^ 1], g_h1[p], g_h1[p ^ 1], g_c1,
                xs0, xs1, cm, biasS4 + 12, b, jj, q, j0);
        gbar();
        if (blockIdx.x < 64)
            fc_step(fcrow, fcbias, g_h1[p ^ 1], out, d, xs0, xs1, cm, blockIdx.x);
        gbar();
    }
}

extern "C" void kernel_launch(void* const* d_in, const int* in_sizes, int n_in,
                              void* d_out, int out_size) {
    const size_t SMEM = 47488 * sizeof(float);   // 189,952 B
    cudaFuncSetAttribute(lstm_persist, cudaFuncAttributeMaxDynamicSharedMemorySize,
                         (int)SMEM);
    lstm_persist<<<NB, THR, SMEM>>>(
        (const float*)d_in[0],
        (const float*)d_in[1],  (const float*)d_in[2],
        (const float*)d_in[3],  (const float*)d_in[4],
        (const float*)d_in[5],  (const float*)d_in[6],
        (const float*)d_in[7],  (const float*)d_in[8],
        (const float*)d_in[9],  (const float*)d_in[10],
        (const float*)d_in[11], (const float*)d_in[12],
        (const float*)d_in[13], (const float*)d_in[14],
        (const float*)d_in[15], (const float*)d_in[16],
        (const float*)d_in[17], (const float*)d_in[18],
        (float*)d_out);
}

// round 10
// speedup vs baseline: 1.3521x; 1.0436x over previous
#include <cuda_runtime.h>

#define HD   512
#define BB   64
#define TT   512
#define FUT  96
#define FF   64
#define NB   128
#define THR  512
#define XSTR 132          // xs row stride (floats): conflict-free reads

typedef unsigned long long u64;

// Persistent state. h stored ROW-MAJOR [b][j] (cp.async-friendly); c stays [j][b].
__device__ float g_h0r[2][BB * HD];
__device__ float g_h1r[2][BB * HD];
__device__ float g_c0[HD * BB];
__device__ float g_c1[HD * BB];
__device__ float g_decx[BB * FF];      // [b][f]
__device__ unsigned g_bar_cnt;
__device__ unsigned g_bar_gen;

__device__ __forceinline__ void fma2(u64 &acc, u64 a, u64 b) {
    asm("fma.rn.f32x2 %0, %1, %2, %0;" : "+l"(acc) : "l"(a), "l"(b));
}
__device__ __forceinline__ float unpack_sum(u64 a) {
    float lo, hi;
    asm("mov.b64 {%0,%1}, %2;" : "=f"(lo), "=f"(hi) : "l"(a));
    return lo + hi;
}
__device__ __forceinline__ float sigm(float x)  { return __fdividef(1.f, 1.f + __expf(-x)); }
__device__ __forceinline__ float tanh_(float x) { return __fdividef(2.f, 1.f + __expf(-2.f * x)) - 1.f; }

__device__ __forceinline__ void gbar() {
    __syncthreads();
    if (threadIdx.x == 0) {
        unsigned gen = *(volatile unsigned*)&g_bar_gen;
        __threadfence();
        unsigned arrived = atomicAdd(&g_bar_cnt, 1u);
        if (arrived == NB - 1) {
            atomicExch(&g_bar_cnt, 0u);
            __threadfence();
            *(volatile unsigned*)&g_bar_gen = gen + 1u;
        } else {
            while (*(volatile unsigned*)&g_bar_gen == gen) { }
            __threadfence();
        }
    }
    __syncthreads();
}

// ---------------- cp.async plumbing ----------------
__device__ __forceinline__ void cpa16(unsigned s, const float* g) {
    asm volatile("cp.async.cg.shared.global [%0], [%1], 16;" :: "r"(s), "l"(g));
}
__device__ __forceinline__ void cp_commit() { asm volatile("cp.async.commit_group;"); }
__device__ __forceinline__ void cp_wait1()  { asm volatile("cp.async.wait_group 1;"); }

struct Bufs { float *f0, *f1, *f2; unsigned s0, s1, s2; };
__device__ __forceinline__ float*   self(const Bufs& B, int r) { return r == 0 ? B.f0 : (r == 1 ? B.f1 : B.f2); }
__device__ __forceinline__ unsigned selu(const Bufs& B, int r) { return r == 0 ? B.s0 : (r == 1 ? B.s1 : B.s2); }

// 128-k chunk from row-major h (row stride HD floats): 4 x 16B per thread.
__device__ __forceinline__ void issue128(unsigned sbuf, const float* __restrict__ g, int k0) {
    int b = threadIdx.x >> 3, m = threadIdx.x & 7;
    const float* gp = g + (size_t)b * HD + k0 + 4 * m;
    unsigned sp = sbuf + (unsigned)(b * XSTR + 4 * m) * 4u;
#pragma unroll
    for (int i = 0; i < 4; i++) cpa16(sp + 128u * i, gp + 32 * i);
    cp_commit();
}
// 64-k chunk, arbitrary row stride rs (floats): 2 x 16B per thread.
__device__ __forceinline__ void issue64(unsigned sbuf, const float* __restrict__ g, int rs) {
    int b = threadIdx.x >> 3, m = threadIdx.x & 7;
    const float* gp = g + (size_t)b * rs + 4 * m;
    unsigned sp = sbuf + (unsigned)(b * XSTR + 4 * m) * 4u;
    cpa16(sp, gp);
    cpa16(sp + 128u, gp + 32);
    cp_commit();
}

// ---------------- gate accumulation ----------------
// x reads: warp spans 4 jj x 8 b_lo -> 1 wf each; w: 4 jj at stride 516/72 -> 1 wf.
__device__ __forceinline__ void acc128(u64 acc[8], const float* xbuf, const float* w, int b, int q) {
    const float* xa = xbuf + b * XSTR + q * 32;
    const float* xb = xa + 32 * XSTR;
#pragma unroll
    for (int s = 0; s < 8; s++) {
        ulonglong2 xv = *(const ulonglong2*)(xa + 4 * s);
        ulonglong2 yv = *(const ulonglong2*)(xb + 4 * s);
        ulonglong2 wv;
        wv = *(const ulonglong2*)(w + 4 * s);
        fma2(acc[0], xv.x, wv.x); fma2(acc[0], xv.y, wv.y);
        fma2(acc[1], yv.x, wv.x); fma2(acc[1], yv.y, wv.y);
        wv = *(const ulonglong2*)(w + 2064 + 4 * s);
        fma2(acc[2], xv.x, wv.x); fma2(acc[2], xv.y, wv.y);
        fma2(acc[3], yv.x, wv.x); fma2(acc[3], yv.y, wv.y);
        wv = *(const ulonglong2*)(w + 4128 + 4 * s);
        fma2(acc[4], xv.x, wv.x); fma2(acc[4], xv.y, wv.y);
        fma2(acc[5], yv.x, wv.x); fma2(acc[5], yv.y, wv.y);
        wv = *(const ulonglong2*)(w + 6192 + 4 * s);
        fma2(acc[6], xv.x, wv.x); fma2(acc[6], xv.y, wv.y);
        fma2(acc[7], yv.x, wv.x); fma2(acc[7], yv.y, wv.y);
    }
}
// Dual: same x chunk feeds two weight sets (L1 x-part + L0 recurrent).
__device__ __forceinline__ void acc128d(u64 a1[8], u64 a0[8], const float* xbuf,
                                        const float* w1, const float* w0, int b, int q) {
    const float* xa = xbuf + b * XSTR + q * 32;
    const float* xb = xa + 32 * XSTR;
#pragma unroll
    for (int s = 0; s < 8; s++) {
        ulonglong2 xv = *(const ulonglong2*)(xa + 4 * s);
        ulonglong2 yv = *(const ulonglong2*)(xb + 4 * s);
        ulonglong2 wv;
        wv = *(const ulonglong2*)(w1 + 4 * s);
        fma2(a1[0], xv.x, wv.x); fma2(a1[0], xv.y, wv.y);
        fma2(a1[1], yv.x, wv.x); fma2(a1[1], yv.y, wv.y);
        wv = *(const ulonglong2*)(w1 + 2064 + 4 * s);
        fma2(a1[2], xv.x, wv.x); fma2(a1[2], xv.y, wv.y);
        fma2(a1[3], yv.x, wv.x); fma2(a1[3], yv.y, wv.y);
        wv = *(const ulonglong2*)(w1 + 4128 + 4 * s);
        fma2(a1[4], xv.x, wv.x); fma2(a1[4], xv.y, wv.y);
        fma2(a1[5], yv.x, wv.x); fma2(a1[5], yv.y, wv.y);
        wv = *(const ulonglong2*)(w1 + 6192 + 4 * s);
        fma2(a1[6], xv.x, wv.x); fma2(a1[6], xv.y, wv.y);
        fma2(a1[7], yv.x, wv.x); fma2(a1[7], yv.y, wv.y);
        wv = *(const ulonglong2*)(w0 + 4 * s);
        fma2(a0[0], xv.x, wv.x); fma2(a0[0], xv.y, wv.y);
        fma2(a0[1], yv.x, wv.x); fma2(a0[1], yv.y, wv.y);
        wv = *(const ulonglong2*)(w0 + 2064 + 4 * s);
        fma2(a0[2], xv.x, wv.x); fma2(a0[2], xv.y, wv.y);
        fma2(a0[3], yv.x, wv.x); fma2(a0[3], yv.y, wv.y);
        wv = *(const ulonglong2*)(w0 + 4128 + 4 * s);
        fma2(a0[4], xv.x, wv.x); fma2(a0[4], xv.y, wv.y);
        fma2(a0[5], yv.x, wv.x); fma2(a0[5], yv.y, wv.y);
        wv = *(const ulonglong2*)(w0 + 6192 + 4 * s);
        fma2(a0[6], xv.x, wv.x); fma2(a0[6], xv.y, wv.y);
        fma2(a0[7], yv.x, wv.x); fma2(a0[7], yv.y, wv.y);
    }
}
// 64-k input chunk (W stride 72, gate stride 288); q covers 16 k.
__device__ __forceinline__ void acc64k(u64 acc[8], const float* xbuf, const float* w, int b, int q) {
    const float* xa = xbuf + b * XSTR + q * 16;
    const float* xb = xa + 32 * XSTR;
#pragma unroll
    for (int s = 0; s < 4; s++) {
        ulonglong2 xv = *(const ulonglong2*)(xa + 4 * s);
        ulonglong2 yv = *(const ulonglong2*)(xb + 4 * s);
        ulonglong2 wv;
        wv = *(const ulonglong2*)(w + 4 * s);
        fma2(acc[0], xv.x, wv.x); fma2(acc[0], xv.y, wv.y);
        fma2(acc[1], yv.x, wv.x); fma2(acc[1], yv.y, wv.y);
        wv = *(const ulonglong2*)(w + 288 + 4 * s);
        fma2(acc[2], xv.x, wv.x); fma2(acc[2], xv.y, wv.y);
        fma2(acc[3], yv.x, wv.x); fma2(acc[3], yv.y, wv.y);
        wv = *(const ulonglong2*)(w + 576 + 4 * s);
        fma2(acc[4], xv.x, wv.x); fma2(acc[4], xv.y, wv.y);
        fma2(acc[5], yv.x, wv.x); fma2(acc[5], yv.y, wv.y);
        wv = *(const ulonglong2*)(w + 864 + 4 * s);
        fma2(acc[6], xv.x, wv.x); fma2(acc[6], xv.y, wv.y);
        fma2(acc[7], yv.x, wv.x); fma2(acc[7], yv.y, wv.y);
    }
}

// Combine 4 q-partials + gate math + c/h update. h written ROW-MAJOR.
__device__ __forceinline__ void combine(const u64 acc[8], float* cm, const float4* biasS,
                                        float* __restrict__ hrow, float* __restrict__ cbuf,
                                        int b, int jj, int q, int j0) {
    float4* cm4 = (float4*)cm;
    int base = q * 256 + jj * 64 + b;
    cm4[base]      = make_float4(unpack_sum(acc[0]), unpack_sum(acc[2]),
                                 unpack_sum(acc[4]), unpack_sum(acc[6]));
    cm4[base + 32] = make_float4(unpack_sum(acc[1]), unpack_sum(acc[3]),
                                 unpack_sum(acc[5]), unpack_sum(acc[7]));
    __syncthreads();
    int tid = threadIdx.x;
    if (tid < 256) {
        int j2 = tid & 3, bb = tid >> 2;
        int s = j2 * 64 + bb;
        float4 a0 = cm4[s], a1 = cm4[s + 256], a2 = cm4[s + 512], a3 = cm4[s + 768];
        float4 bs = biasS[j2];
        float gi = a0.x + a1.x + a2.x + a3.x + bs.x;
        float gf = a0.y + a1.y + a2.y + a3.y + bs.y;
        float gg = a0.z + a1.z + a2.z + a3.z + bs.z;
        float go = a0.w + a1.w + a2.w + a3.w + bs.w;
        int ci = (j0 + j2) * 64 + bb;
        float c = sigm(gf) * cbuf[ci] + sigm(gi) * tanh_(gg);
        cbuf[ci] = c;
        hrow[(size_t)bb * HD + j0 + j2] = sigm(go) * tanh_(c);
    }
    __syncthreads();
}

// ---------------- cells (cp.async 3-buffer, 2-ahead pipeline) ----------------

// L0-style: chunks 0-3 = h recurrent (Wh), chunk 4 = 64-wide input (Wi).
__device__ __noinline__ void cellA(const float* Wh, const float* Wi,
                                   const float* __restrict__ hsrc,
                                   const float* __restrict__ x64, int x64s,
                                   float* hnext, float* cbuf, const float4* biasS,
                                   const Bufs& B, float* cm, int b, int jj, int q, int j0) {
    u64 acc[8] = {};
    issue128(B.s0, hsrc, 0);
    issue128(B.s1, hsrc, 128);
#pragma unroll 1
    for (int c = 0; c <= 4; c++) {
        cp_wait1();
        __syncthreads();
        int n = c + 2, rn = n % 3;
        if (n < 4)       issue128(selu(B, rn), hsrc, 128 * n);
        else if (n == 4) issue64(selu(B, rn), x64, x64s);
        else             cp_commit();
        const float* xb = self(B, c % 3);
        if (c < 4) acc128(acc, xb, Wh + jj * 516 + c * 128 + q * 32, b, q);
        else       acc64k(acc, xb, Wi + jj * 72 + q * 16, b, q);
    }
    combine(acc, cm, biasS, hnext, cbuf, b, jj, q, j0);
}

// L1-style: chunks 0-3 = x-part (h0 new, Wxi), 4-7 = h1 recurrent (Whh).
__device__ __noinline__ void cellB(const float* Wxi, const float* Whh,
                                   const float* __restrict__ xh,
                                   const float* __restrict__ hh,
                                   float* hnext, float* cbuf, const float4* biasS,
                                   const Bufs& B, float* cm, int b, int jj, int q, int j0) {
    u64 acc[8] = {};
    issue128(B.s0, xh, 0);
    issue128(B.s1, xh, 128);
#pragma unroll 1
    for (int c = 0; c < 8; c++) {
        cp_wait1();
        __syncthreads();
        int n = c + 2, rn = n % 3;
        if (n < 4)      issue128(selu(B, rn), xh, 128 * n);
        else if (n < 8) issue128(selu(B, rn), hh, 128 * (n - 4));
        else            cp_commit();
        const float* xb = self(B, c % 3);
        const float* W = (c < 4) ? (Wxi + c * 128) : (Whh + (c - 4) * 128);
        acc128(acc, xb, W + jj * 516 + q * 32, b, q);
    }
    combine(acc, cm, biasS, hnext, cbuf, b, jj, q, j0);
}

// Fused encoder step: L1(t) and L0(t+1) share the h0(t) chunks (dual acc).
__device__ __noinline__ void dualstep(const float* W1i, const float* W1h,
                                      const float* W0i, const float* W0h,
                                      const float* __restrict__ h0c,
                                      const float* __restrict__ h1c,
                                      const float* __restrict__ xin, int xins,
                                      float* h1n, float* h0n,
                                      const float4* bias1, const float4* bias0,
                                      const Bufs& B, float* cm, int b, int jj, int q, int j0) {
    u64 a1[8] = {}, a0[8] = {};
    issue128(B.s0, h0c, 0);
    issue128(B.s1, h0c, 128);
#pragma unroll 1
    for (int c = 0; c <= 8; c++) {
        cp_wait1();
        __syncthreads();
        int n = c + 2, rn = n % 3;
        if (n < 4)       issue128(selu(B, rn), h0c, 128 * n);
        else if (n < 8)  issue128(selu(B, rn), h1c, 128 * (n - 4));
        else if (n == 8) issue64(selu(B, rn), xin, xins);
        else             cp_commit();
        const float* xb = self(B, c % 3);
        if (c < 4)
            acc128d(a1, a0, xb, W1i + jj * 516 + c * 128 + q * 32,
                    W0h + jj * 516 + c * 128 + q * 32, b, q);
        else if (c < 8)
            acc128(a1, xb, W1h + jj * 516 + (c - 4) * 128 + q * 32, b, q);
        else
            acc64k(a0, xb, W0i + jj * 72 + q * 16, b, q);
    }
    combine(a1, cm, bias1, h1n, g_c1, b, jj, q, j0);
    combine(a0, cm, bias0, h0n, g_c0, b, jj, q, j0);
}

// Decoder FC (CTAs < 64): out[:,d,f] = h1 . fcrow + fcb[f]; feedback into g_decx.
__device__ __noinline__ void fcstep(const float* fcrow, float fcbias,
                                    const float* __restrict__ h1,
                                    float* __restrict__ out, int d,
                                    const Bufs& B, float* cm, int f) {
    int tid = threadIdx.x, bq = tid & 63, q8 = tid >> 6;
    u64 acc = 0ull;
    issue128(B.s0, h1, 0);
    issue128(B.s1, h1, 128);
#pragma unroll 1
    for (int c = 0; c < 4; c++) {
        cp_wait1();
        __syncthreads();
        int n = c + 2;
        if (n < 4) issue128(selu(B, n % 3), h1, 128 * n);
        else       cp_commit();
        if ((q8 >> 1) == c) {
            const float* x = self(B, c % 3) + (size_t)bq * XSTR + (q8 & 1) * 64;
            const float* w = fcrow + q8 * 64;
#pragma unroll
            for (int s = 0; s < 16; s++) {
                ulonglong2 xv = *(const ulonglong2*)(x + 4 * s);
                ulonglong2 wv = *(const ulonglong2*)(w + 4 * s);
                fma2(acc, xv.x, wv.x); fma2(acc, xv.y, wv.y);
            }
        }
    }
    __syncthreads();
    cm[q8 * 64 + bq] = unpack_sum(acc);
    __syncthreads();
    if (q8 == 0) {
        float v = fcbias;
#pragma unroll
        for (int m = 0; m < 8; m++) v += cm[m * 64 + bq];
        out[(size_t)bq * (FUT * FF) + (size_t)d * FF + f] = v;
        g_decx[bq * 64 + f] = v;
    }
    __syncthreads();
}

// Copy 16 weight rows (gate-major: row = g*4+jj), padded row stride RS.
__device__ __forceinline__ void loadW(float* dst, const float* __restrict__ src,
                                      int K, int RS, int j0) {
    int Kq = K >> 2, n = 16 * Kq;
    for (int i = threadIdx.x; i < n; i += THR) {
        int rr = i / Kq, kq = i - rr * Kq;
        int g = rr >> 2, j2 = rr & 3;
        float4 v = *(const float4*)(src + (size_t)(g * HD + j0 + j2) * K + kq * 4);
        *(float4*)(dst + (size_t)rr * RS + kq * 4) = v;
    }
}

// SMEM (floats): W0i@0(1152) W0h@1152(8256) W1i@9408(8256) W1h@17664(8256)
//  fcrow@25920(512) biasS@26432(64) cm@26496(4096)
//  xs0@30592 xs1@39040 xs2@47488 (3 x 8448) -> 55936 fl = 223,744 B
__global__ void __launch_bounds__(THR, 1)
lstm_persist(const float* __restrict__ in,
             const float* __restrict__ eWih0, const float* __restrict__ eWhh0,
             const float* __restrict__ ebih0, const float* __restrict__ ebhh0,
             const float* __restrict__ eWih1, const float* __restrict__ eWhh1,
             const float* __restrict__ ebih1, const float* __restrict__ ebhh1,
             const float* __restrict__ dWih0, const float* __restrict__ dWhh0,
             const float* __restrict__ dbih0, const float* __restrict__ dbhh0,
             const float* __restrict__ dWih1, const float* __restrict__ dWhh1,
             const float* __restrict__ dbih1, const float* __restrict__ dbhh1,
             const float* __restrict__ fcW,   const float* __restrict__ fcb,
             float* __restrict__ out) {
    extern __shared__ float sm[];
    float*  W0i    = sm;
    float*  W0h    = sm + 1152;
    float*  W1i    = sm + 9408;
    float*  W1h    = sm + 17664;
    float*  fcrow  = sm + 25920;
    float4* biasS4 = (float4*)(sm + 26432);
    float*  cm     = sm + 26496;

    Bufs B;
    B.f0 = sm + 30592; B.f1 = sm + 39040; B.f2 = sm + 47488;
    B.s0 = (unsigned)__cvta_generic_to_shared(B.f0);
    B.s1 = (unsigned)__cvta_generic_to_shared(B.f1);
    B.s2 = (unsigned)__cvta_generic_to_shared(B.f2);

    const int tid   = threadIdx.x;
    const int q     = tid >> 7;
    const int t7    = tid & 127;
    const int b_mid = t7 >> 5;
    const int jj    = (t7 >> 3) & 3;
    const int b_lo  = t7 & 7;
    const int b     = b_mid * 8 + b_lo;      // 0..31 (also handles b+32)
    const int j0    = blockIdx.x * 4;
    const int j     = j0 + jj;

    loadW(W0i, eWih0, 64, 72,  j0);
    loadW(W0h, eWhh0, HD, 516, j0);
    loadW(W1i, eWih1, HD, 516, j0);
    loadW(W1h, eWhh1, HD, 516, j0);
    float fcbias = 0.f;
    if (blockIdx.x < 64) {
        for (int i = tid; i < HD; i += THR) fcrow[i] = fcW[(size_t)blockIdx.x * HD + i];
        fcbias = fcb[blockIdx.x];
    }

    {   // zero persistent state (unique coverage across grid)
        int i = blockIdx.x * THR + tid;      // 0..65535
        if (i < 32768) { g_h0r[0][i] = 0.f; g_c0[i] = 0.f; }
        else           { g_h1r[0][i - 32768] = 0.f; g_c1[i - 32768] = 0.f; }
    }

    if (q == 0 && b == 0) {   // combined biases (4 threads, one per jj)
        biasS4[jj] = make_float4(ebih0[j] + ebhh0[j], ebih0[HD + j] + ebhh0[HD + j],
                                 ebih0[2 * HD + j] + ebhh0[2 * HD + j],
                                 ebih0[3 * HD + j] + ebhh0[3 * HD + j]);
        biasS4[4 + jj] = make_float4(ebih1[j] + ebhh1[j], ebih1[HD + j] + ebhh1[HD + j],
                                     ebih1[2 * HD + j] + ebhh1[2 * HD + j],
                                     ebih1[3 * HD + j] + ebhh1[3 * HD + j]);
        biasS4[8 + jj] = make_float4(dbih0[j] + dbhh0[j], dbih0[HD + j] + dbhh0[HD + j],
                                     dbih0[2 * HD + j] + dbhh0[2 * HD + j],
                                     dbih0[3 * HD + j] + dbhh0[3 * HD + j]);
        biasS4[12 + jj] = make_float4(dbih1[j] + dbhh1[j], dbih1[HD + j] + dbhh1[HD + j],
                                      dbih1[2 * HD + j] + dbhh1[2 * HD + j],
                                      dbih1[3 * HD + j] + dbhh1[3 * HD + j]);
    }

    gbar();

    // ===================== encoder =====================
    // L0(t=0): h0 prev = zeros (slot0) -> h0(0) into slot1
    cellA(W0h, W0i, g_h0r[0], in, TT * FF, g_h0r[1], g_c0, biasS4,
          B, cm, b, jj, q, j0);
    gbar();
    int s0 = 1, s1 = 0;
#pragma unroll 1
    for (int t = 0; t < TT - 1; t++) {
        dualstep(W1i, W1h, W0i, W0h,
                 g_h0r[s0], g_h1r[s1], in + (size_t)(t + 1) * FF, TT * FF,
                 g_h1r[s1 ^ 1], g_h0r[s0 ^ 1],
                 biasS4 + 4, biasS4, B, cm, b, jj, q, j0);
        s0 ^= 1; s1 ^= 1;
        gbar();
    }
    cellB(W1i, W1h, g_h0r[s0], g_h1r[s1], g_h1r[s1 ^ 1], g_c1, biasS4 + 4,
          B, cm, b, jj, q, j0);
    s1 ^= 1;
    gbar();

    // swap to decoder weights
    loadW(W0i, dWih0, 64, 72,  j0);
    loadW(W0h, dWhh0, HD, 516, j0);
    loadW(W1i, dWih1, HD, 516, j0);
    loadW(W1h, dWhh1, HD, 516, j0);
    __syncthreads();

    // ===================== decoder =====================
#pragma unroll 1
    for (int d = 0; d < FUT; d++) {
        if (d == 0)
            cellA(W0h, W0i, g_h0r[s0], in + (size_t)(TT - 1) * FF, TT * FF,
                  g_h0r[s0 ^ 1], g_c0, biasS4 + 8, B, cm, b, jj, q, j0);
        else
            cellA(W0h, W0i, g_h0r[s0], g_decx, FF,
                  g_h0r[s0 ^ 1], g_c0, biasS4 + 8, B, cm, b, jj, q, j0);
        s0 ^= 1;
        gbar();
        cellB(W1i, W1h, g_h0r[s0], g_h1r[s1], g_h1r[s1 ^ 1], g_c1, biasS4 + 12,
              B, cm, b, jj, q, j0);
        s1 ^= 1;
        gbar();
        if (blockIdx.x < 64)
            fcstep(fcrow, fcbias, g_h1r[s1], out, d, B, cm, blockIdx.x);
        gbar();
    }
}

extern "C" void kernel_launch(void* const* d_in, const int* in_sizes, int n_in,
                              void* d_out, int out_size) {
    const size_t SMEM = 55936 * sizeof(float);   // 223,744 B
    cudaFuncSetAttribute(lstm_persist, cudaFuncAttributeMaxDynamicSharedMemorySize,
                         (int)SMEM);
    lstm_persist<<<NB, THR, SMEM>>>(
        (const float*)d_in[0],
        (const float*)d_in[1],  (const float*)d_in[2],
        (const float*)d_in[3],  (const float*)d_in[4],
        (const float*)d_in[5],  (const float*)d_in[6],
        (const float*)d_in[7],  (const float*)d_in[8],
        (const float*)d_in[9],  (const float*)d_in[10],
        (const float*)d_in[11], (const float*)d_in[12],
        (const float*)d_in[13], (const float*)d_in[14],
        (const float*)d_in[15], (const float*)d_in[16],
        (const float*)d_in[17], (const float*)d_in[18],
        (float*)d_out);
}